// round 1
// baseline (speedup 1.0000x reference)
#include <cuda_runtime.h>
#include <math.h>

// Problem constants
#define BATCH   16
#define SEQ     1024
#define CH      1024
#define HEADS   16
#define DH      64
#define TOKENS  (BATCH*SEQ)      // 16384
#define LN_EPS  1e-6f
#define QSCALE  0.125f           // Dh^-0.5 = 64^-0.5

// Scratch (device globals: allocation-free per harness rules)
__device__ float g_y [TOKENS*CH];
__device__ float g_q [TOKENS*CH];
__device__ float g_k [TOKENS*CH];
__device__ float g_v [TOKENS*CH];
__device__ float g_ao[TOKENS*CH];

// ---------------------------------------------------------------------------
// Kernel 1: LayerNorm over last dim (C=1024), no affine. One block per row.
// 256 threads, one float4 per thread.
// ---------------------------------------------------------------------------
__global__ __launch_bounds__(256) void ln_rows(const float* __restrict__ x,
                                               float* __restrict__ y)
{
    int row = blockIdx.x;
    int t = threadIdx.x;
    const float4* xr = (const float4*)(x + (size_t)row * CH);
    float4* yr = (float4*)(y + (size_t)row * CH);

    float4 v = xr[t];
    float s  = v.x + v.y + v.z + v.w;
    float ss = v.x*v.x + v.y*v.y + v.z*v.z + v.w*v.w;

    #pragma unroll
    for (int o = 16; o; o >>= 1) {
        s  += __shfl_xor_sync(0xFFFFFFFFu, s,  o);
        ss += __shfl_xor_sync(0xFFFFFFFFu, ss, o);
    }
    __shared__ float sh[16];
    int w = t >> 5, l = t & 31;
    if (l == 0) { sh[w] = s; sh[8 + w] = ss; }
    __syncthreads();
    float S = 0.f, SS = 0.f;
    #pragma unroll
    for (int i = 0; i < 8; i++) { S += sh[i]; SS += sh[8 + i]; }

    float mean = S * (1.0f / CH);
    float var  = SS * (1.0f / CH) - mean * mean;
    float inv  = rsqrtf(var + LN_EPS);

    v.x = (v.x - mean) * inv;
    v.y = (v.y - mean) * inv;
    v.z = (v.z - mean) * inv;
    v.w = (v.w - mean) * inv;
    yr[t] = v;
}

// ---------------------------------------------------------------------------
// Kernel 2/5: SGEMM "NT": C[m,n] = sum_k A[m,k]*B[n,k] (+ bias[n]).
// A: MxK row-major, B: NxK row-major (torch Linear weight), C: MxN.
// 128x128 block tile, BK=16, 256 threads, 8x8 per thread.
// ---------------------------------------------------------------------------
template<bool BIAS>
__global__ __launch_bounds__(256) void sgemm_nt(const float* __restrict__ A,
                                                const float* __restrict__ B,
                                                const float* __restrict__ bias,
                                                float* __restrict__ C,
                                                int M, int N, int K)
{
    const int BM = 128, BN = 128, BK = 16;
    __shared__ float As[BK][BM];
    __shared__ float Bs[BK][BN];

    int t  = threadIdx.x;
    int bm = blockIdx.y * BM;
    int bn = blockIdx.x * BN;
    int tx = t & 15;          // 0..15 -> 8 columns each
    int ty = t >> 4;          // 0..15 -> 8 rows each

    const float* Ag = A + (size_t)bm * K;
    const float* Bg = B + (size_t)bn * K;

    float acc[8][8];
    #pragma unroll
    for (int i = 0; i < 8; i++)
        #pragma unroll
        for (int j = 0; j < 8; j++) acc[i][j] = 0.f;

    for (int k0 = 0; k0 < K; k0 += BK) {
        // Load 128x16 tiles of A and B (512 float4 each; 2 per thread)
        #pragma unroll
        for (int i = 0; i < 2; i++) {
            int f   = t + i * 256;      // float4 index
            int row = f >> 2;           // 4 float4 per row
            int kq  = (f & 3) * 4;
            float4 a = *(const float4*)(Ag + (size_t)row * K + k0 + kq);
            As[kq+0][row] = a.x; As[kq+1][row] = a.y;
            As[kq+2][row] = a.z; As[kq+3][row] = a.w;
            float4 b = *(const float4*)(Bg + (size_t)row * K + k0 + kq);
            Bs[kq+0][row] = b.x; Bs[kq+1][row] = b.y;
            Bs[kq+2][row] = b.z; Bs[kq+3][row] = b.w;
        }
        __syncthreads();

        #pragma unroll
        for (int kk = 0; kk < BK; kk++) {
            float a[8], b[8];
            *(float4*)(a)     = *(const float4*)&As[kk][ty*8];
            *(float4*)(a + 4) = *(const float4*)&As[kk][ty*8 + 4];
            *(float4*)(b)     = *(const float4*)&Bs[kk][tx*8];
            *(float4*)(b + 4) = *(const float4*)&Bs[kk][tx*8 + 4];
            #pragma unroll
            for (int i = 0; i < 8; i++)
                #pragma unroll
                for (int j = 0; j < 8; j++)
                    acc[i][j] += a[i] * b[j];
        }
        __syncthreads();
    }

    float bv[8];
    #pragma unroll
    for (int j = 0; j < 8; j++)
        bv[j] = BIAS ? bias[bn + tx*8 + j] : 0.f;

    #pragma unroll
    for (int i = 0; i < 8; i++) {
        int m = bm + ty*8 + i;
        float* Cr = C + (size_t)m * N + bn + tx*8;
        float4 o0, o1;
        o0.x = acc[i][0] + bv[0]; o0.y = acc[i][1] + bv[1];
        o0.z = acc[i][2] + bv[2]; o0.w = acc[i][3] + bv[3];
        o1.x = acc[i][4] + bv[4]; o1.y = acc[i][5] + bv[5];
        o1.z = acc[i][6] + bv[6]; o1.w = acc[i][7] + bv[7];
        *(float4*)(Cr)     = o0;
        *(float4*)(Cr + 4) = o1;
    }
}

// ---------------------------------------------------------------------------
// Kernel 3: per-head LayerNorm over Dh=64 for q (with *0.125) and k, in place.
// One warp per (token, head). blockIdx.y: 0 -> q, 1 -> k.
// ---------------------------------------------------------------------------
__global__ __launch_bounds__(256) void head_ln(float* __restrict__ q,
                                               float* __restrict__ k)
{
    float* base = blockIdx.y ? k : q;
    float sc    = blockIdx.y ? 1.0f : QSCALE;

    int warp = threadIdx.x >> 5;
    int lane = threadIdx.x & 31;
    int idx  = blockIdx.x * 8 + warp;       // 0 .. TOKENS*HEADS-1
    int token = idx >> 4;
    int h     = idx & 15;

    float2* p = (float2*)(base + (size_t)token * CH + h * DH) + lane;
    float2 v = *p;
    float s  = v.x + v.y;
    float ss = v.x*v.x + v.y*v.y;
    #pragma unroll
    for (int o = 16; o; o >>= 1) {
        s  += __shfl_xor_sync(0xFFFFFFFFu, s,  o);
        ss += __shfl_xor_sync(0xFFFFFFFFu, ss, o);
    }
    float mean = s * (1.0f / DH);
    float var  = ss * (1.0f / DH) - mean * mean;
    float inv  = rsqrtf(var + LN_EPS) * sc;
    v.x = (v.x - mean) * inv;
    v.y = (v.y - mean) * inv;
    *p = v;
}

// ---------------------------------------------------------------------------
// Kernel 4: attention with online softmax. One query row per thread.
// blockIdx.x = b*16+h (256), blockIdx.y = q-tile of 256 rows (4). 256 threads.
// ---------------------------------------------------------------------------
__global__ __launch_bounds__(256, 1) void attn_kernel(const float* __restrict__ q,
                                                      const float* __restrict__ k,
                                                      const float* __restrict__ v,
                                                      float* __restrict__ o)
{
    int bh = blockIdx.x;
    int b  = bh >> 4;
    int h  = bh & 15;
    int t  = threadIdx.x;
    int qi = blockIdx.y * 256 + t;

    const float* qrow = q + ((size_t)(b * SEQ + qi)) * CH + h * DH;
    float qr[DH];
    #pragma unroll
    for (int d4 = 0; d4 < DH/4; d4++) {
        float4 f = ((const float4*)qrow)[d4];
        qr[4*d4+0] = f.x; qr[4*d4+1] = f.y; qr[4*d4+2] = f.z; qr[4*d4+3] = f.w;
    }

    float acc[DH];
    #pragma unroll
    for (int d = 0; d < DH; d++) acc[d] = 0.f;
    float m = -INFINITY, l = 0.f;

    __shared__ float Ks[64][DH];
    __shared__ float Vs[64][DH];

    for (int kt = 0; kt < SEQ; kt += 64) {
        __syncthreads();
        #pragma unroll
        for (int i = 0; i < 4; i++) {
            int f   = t + i * 256;   // float4 index within 64x64 tile
            int row = f >> 4;        // 16 float4 per row
            int col = f & 15;
            size_t gro = ((size_t)(b * SEQ + kt + row)) * CH + h * DH;
            ((float4*)Ks[row])[col] = ((const float4*)(k + gro))[col];
            ((float4*)Vs[row])[col] = ((const float4*)(v + gro))[col];
        }
        __syncthreads();

        #pragma unroll 1
        for (int j = 0; j < 64; j++) {
            float s0 = 0.f, s1 = 0.f, s2 = 0.f, s3 = 0.f;
            #pragma unroll
            for (int d4 = 0; d4 < DH/4; d4++) {
                float4 kk = ((const float4*)Ks[j])[d4];
                s0 += qr[4*d4+0] * kk.x;
                s1 += qr[4*d4+1] * kk.y;
                s2 += qr[4*d4+2] * kk.z;
                s3 += qr[4*d4+3] * kk.w;
            }
            float s  = (s0 + s1) + (s2 + s3);
            float mn = fmaxf(m, s);
            float p    = __expf(s - mn);
            float corr = __expf(m - mn);
            l = l * corr + p;
            #pragma unroll
            for (int d4 = 0; d4 < DH/4; d4++) {
                float4 vv = ((const float4*)Vs[j])[d4];
                acc[4*d4+0] = acc[4*d4+0] * corr + p * vv.x;
                acc[4*d4+1] = acc[4*d4+1] * corr + p * vv.y;
                acc[4*d4+2] = acc[4*d4+2] * corr + p * vv.z;
                acc[4*d4+3] = acc[4*d4+3] * corr + p * vv.w;
            }
            m = mn;
        }
    }

    float rl = 1.0f / l;
    float* orow = o + ((size_t)(b * SEQ + qi)) * CH + h * DH;
    #pragma unroll
    for (int d4 = 0; d4 < DH/4; d4++) {
        float4 f;
        f.x = acc[4*d4+0] * rl; f.y = acc[4*d4+1] * rl;
        f.z = acc[4*d4+2] * rl; f.w = acc[4*d4+3] * rl;
        ((float4*)orow)[d4] = f;
    }
}

// ---------------------------------------------------------------------------
// Launch
// ---------------------------------------------------------------------------
extern "C" void kernel_launch(void* const* d_in, const int* in_sizes, int n_in,
                              void* d_out, int out_size)
{
    const float* x  = (const float*)d_in[0];
    const float* Wq = (const float*)d_in[1];
    const float* Wk = (const float*)d_in[2];
    const float* Wv = (const float*)d_in[3];
    const float* Wp = (const float*)d_in[4];
    const float* bp = (const float*)d_in[5];
    float* out = (float*)d_out;

    float *p_y, *p_q, *p_k, *p_v, *p_ao;
    cudaGetSymbolAddress((void**)&p_y,  g_y);
    cudaGetSymbolAddress((void**)&p_q,  g_q);
    cudaGetSymbolAddress((void**)&p_k,  g_k);
    cudaGetSymbolAddress((void**)&p_v,  g_v);
    cudaGetSymbolAddress((void**)&p_ao, g_ao);

    // 1. Pre-LN
    ln_rows<<<TOKENS, 256>>>(x, p_y);

    // 2. QKV projections: [16384,1024] x [1024,1024]^T
    dim3 gqkv(CH / 128, TOKENS / 128);
    sgemm_nt<false><<<gqkv, 256>>>(p_y, Wq, nullptr, p_q, TOKENS, CH, CH);
    sgemm_nt<false><<<gqkv, 256>>>(p_y, Wk, nullptr, p_k, TOKENS, CH, CH);
    sgemm_nt<false><<<gqkv, 256>>>(p_y, Wv, nullptr, p_v, TOKENS, CH, CH);

    // 3. Per-head LN on q (with scale) and k
    head_ln<<<dim3(TOKENS * HEADS / 8, 2), 256>>>(p_q, p_k);

    // 4. Attention
    attn_kernel<<<dim3(BATCH * HEADS, SEQ / 256), 256>>>(p_q, p_k, p_v, p_ao);

    // 5. Output projection + bias
    sgemm_nt<true><<<gqkv, 256>>>(p_ao, Wp, bp, out, TOKENS, CH, CH);
}

// round 2
// speedup vs baseline: 1.5779x; 1.5779x over previous
#include <cuda_runtime.h>
#include <cuda_bf16.h>
#include <math.h>
#include <stdint.h>

// Problem constants
#define BATCH   16
#define SEQ     1024
#define CH      1024
#define HEADS   16
#define DH      64
#define TOKENS  (BATCH*SEQ)      // 16384
#define LN_EPS  1e-6f
#define QSCALE  0.125f           // Dh^-0.5

// Scratch (device globals: allocation-free per harness rules)
__device__ float g_y [TOKENS*CH];
__device__ float g_q [TOKENS*CH];
__device__ float g_k [TOKENS*CH];
__device__ float g_v [TOKENS*CH];
__device__ float g_ao[TOKENS*CH];

// ---------------------------------------------------------------------------
// helpers: mma / ldmatrix
// ---------------------------------------------------------------------------
__device__ __forceinline__ uint32_t smem_u32(const void* p) {
    return (uint32_t)__cvta_generic_to_shared(p);
}
__device__ __forceinline__ void ldsm_x4(uint32_t& r0, uint32_t& r1,
                                        uint32_t& r2, uint32_t& r3, uint32_t addr) {
    asm volatile("ldmatrix.sync.aligned.m8n8.x4.shared.b16 {%0,%1,%2,%3},[%4];"
                 : "=r"(r0), "=r"(r1), "=r"(r2), "=r"(r3) : "r"(addr));
}
__device__ __forceinline__ void mma_bf16(float& c0, float& c1, float& c2, float& c3,
                                         uint32_t a0, uint32_t a1, uint32_t a2, uint32_t a3,
                                         uint32_t b0, uint32_t b1) {
    asm volatile("mma.sync.aligned.m16n8k16.row.col.f32.bf16.bf16.f32 "
                 "{%0,%1,%2,%3},{%4,%5,%6,%7},{%8,%9},{%0,%1,%2,%3};"
                 : "+f"(c0), "+f"(c1), "+f"(c2), "+f"(c3)
                 : "r"(a0), "r"(a1), "r"(a2), "r"(a3), "r"(b0), "r"(b1));
}
__device__ __forceinline__ void split_pack(float4 f, uint32_t& h01, uint32_t& h23,
                                           uint32_t& l01, uint32_t& l23) {
    __nv_bfloat16 h0 = __float2bfloat16(f.x);
    __nv_bfloat16 h1 = __float2bfloat16(f.y);
    __nv_bfloat16 h2 = __float2bfloat16(f.z);
    __nv_bfloat16 h3 = __float2bfloat16(f.w);
    __nv_bfloat16 l0 = __float2bfloat16(f.x - __bfloat162float(h0));
    __nv_bfloat16 l1 = __float2bfloat16(f.y - __bfloat162float(h1));
    __nv_bfloat16 l2 = __float2bfloat16(f.z - __bfloat162float(h2));
    __nv_bfloat16 l3 = __float2bfloat16(f.w - __bfloat162float(h3));
    h01 = (uint32_t)__bfloat16_as_ushort(h0) | ((uint32_t)__bfloat16_as_ushort(h1) << 16);
    h23 = (uint32_t)__bfloat16_as_ushort(h2) | ((uint32_t)__bfloat16_as_ushort(h3) << 16);
    l01 = (uint32_t)__bfloat16_as_ushort(l0) | ((uint32_t)__bfloat16_as_ushort(l1) << 16);
    l23 = (uint32_t)__bfloat16_as_ushort(l2) | ((uint32_t)__bfloat16_as_ushort(l3) << 16);
}

// ---------------------------------------------------------------------------
// Kernel 1: LayerNorm over last dim (C=1024), no affine. One block per row.
// ---------------------------------------------------------------------------
__global__ __launch_bounds__(256) void ln_rows(const float* __restrict__ x,
                                               float* __restrict__ y)
{
    int row = blockIdx.x;
    int t = threadIdx.x;
    const float4* xr = (const float4*)(x + (size_t)row * CH);
    float4* yr = (float4*)(y + (size_t)row * CH);

    float4 v = xr[t];
    float s  = v.x + v.y + v.z + v.w;
    float ss = v.x*v.x + v.y*v.y + v.z*v.z + v.w*v.w;

    #pragma unroll
    for (int o = 16; o; o >>= 1) {
        s  += __shfl_xor_sync(0xFFFFFFFFu, s,  o);
        ss += __shfl_xor_sync(0xFFFFFFFFu, ss, o);
    }
    __shared__ float sh[16];
    int w = t >> 5, l = t & 31;
    if (l == 0) { sh[w] = s; sh[8 + w] = ss; }
    __syncthreads();
    float S = 0.f, SS = 0.f;
    #pragma unroll
    for (int i = 0; i < 8; i++) { S += sh[i]; SS += sh[8 + i]; }

    float mean = S * (1.0f / CH);
    float var  = SS * (1.0f / CH) - mean * mean;
    float inv  = rsqrtf(var + LN_EPS);

    v.x = (v.x - mean) * inv;
    v.y = (v.y - mean) * inv;
    v.z = (v.z - mean) * inv;
    v.w = (v.w - mean) * inv;
    yr[t] = v;
}

// ---------------------------------------------------------------------------
// Kernel 2: split-bf16 tensor-core GEMM (NT): C[m,n] = sum_k A[m,k]*B[n,k] (+bias)
// fp32 inputs are split into bf16 hi+lo during the smem stage; per tile we do
// 3 mma passes (hi*hi + hi*lo + lo*hi), residual ~2^-18.
// 128x128x32 block tile, 256 threads (8 warps, 2x4), warp tile 64x32.
// ---------------------------------------------------------------------------
#define BK   32
#define PADK 40   // bf16 elements per smem row (conflict-free ldmatrix)

template<bool BIAS, bool QKV3>
__global__ __launch_bounds__(256) void gemm_bf16s(const float* __restrict__ A,
                                                  const float* __restrict__ B0,
                                                  const float* __restrict__ B1,
                                                  const float* __restrict__ B2,
                                                  const float* __restrict__ bias,
                                                  float* __restrict__ C0,
                                                  float* __restrict__ C1,
                                                  float* __restrict__ C2,
                                                  int M, int N, int K)
{
    __shared__ __align__(16) uint16_t As_h[128 * PADK];
    __shared__ __align__(16) uint16_t As_l[128 * PADK];
    __shared__ __align__(16) uint16_t Bs_h[128 * PADK];
    __shared__ __align__(16) uint16_t Bs_l[128 * PADK];

    const float* B = B0;
    float* C = C0;
    if (QKV3) {
        if (blockIdx.z == 1) { B = B1; C = C1; }
        else if (blockIdx.z == 2) { B = B2; C = C2; }
    }

    int t    = threadIdx.x;
    int lane = t & 31;
    int warp = t >> 5;
    int wm64 = (warp >> 2) * 64;   // warp row base in tile
    int wn32 = (warp & 3) * 32;    // warp col base in tile
    int bm = blockIdx.y * 128;
    int bn = blockIdx.x * 128;

    const float* Ag = A + (size_t)bm * K;
    const float* Bg = B + (size_t)bn * K;

    float acc[4][4][4];
    #pragma unroll
    for (int i = 0; i < 4; i++)
        #pragma unroll
        for (int j = 0; j < 4; j++)
            #pragma unroll
            for (int c = 0; c < 4; c++) acc[i][j][c] = 0.f;

    // staged global loads: 4 float4 for A, 4 for B per thread
    float4 ra[4], rb[4];
    int ldrow[4], ldc4[4];
    #pragma unroll
    for (int i = 0; i < 4; i++) {
        int f = t + i * 256;
        ldrow[i] = f >> 3;        // 8 float4 per 32-float row
        ldc4[i]  = f & 7;
    }

    #pragma unroll
    for (int i = 0; i < 4; i++) {
        ra[i] = *(const float4*)(Ag + (size_t)ldrow[i] * K + ldc4[i] * 4);
        rb[i] = *(const float4*)(Bg + (size_t)ldrow[i] * K + ldc4[i] * 4);
    }

    // ldmatrix source addresses (per-lane, fixed except kc offset)
    int a_r    = lane & 15;
    int a_koff = (lane >> 4) << 3;
    int b_n    = (lane & 7) + ((lane >> 4) << 3);
    int b_koff = ((lane >> 3) & 1) << 3;

    for (int k0 = 0; k0 < K; k0 += BK) {
        // store staged tile (converted) to smem
        #pragma unroll
        for (int i = 0; i < 4; i++) {
            uint32_t h01, h23, l01, l23;
            int off = ldrow[i] * PADK + ldc4[i] * 4;
            split_pack(ra[i], h01, h23, l01, l23);
            *(uint2*)&As_h[off] = make_uint2(h01, h23);
            *(uint2*)&As_l[off] = make_uint2(l01, l23);
            split_pack(rb[i], h01, h23, l01, l23);
            *(uint2*)&Bs_h[off] = make_uint2(h01, h23);
            *(uint2*)&Bs_l[off] = make_uint2(l01, l23);
        }
        __syncthreads();

        // issue next tile's global loads early (latency hidden by mma below)
        if (k0 + BK < K) {
            #pragma unroll
            for (int i = 0; i < 4; i++) {
                ra[i] = *(const float4*)(Ag + (size_t)ldrow[i] * K + k0 + BK + ldc4[i] * 4);
                rb[i] = *(const float4*)(Bg + (size_t)ldrow[i] * K + k0 + BK + ldc4[i] * 4);
            }
        }

        #pragma unroll
        for (int kc = 0; kc < 2; kc++) {
            int ko = kc * 16;
            uint32_t ah[4][4], al[4][4], bh[4][2], bl[4][2];
            #pragma unroll
            for (int mt = 0; mt < 4; mt++) {
                int off = (wm64 + mt * 16 + a_r) * PADK + ko + a_koff;
                ldsm_x4(ah[mt][0], ah[mt][1], ah[mt][2], ah[mt][3], smem_u32(&As_h[off]));
                ldsm_x4(al[mt][0], al[mt][1], al[mt][2], al[mt][3], smem_u32(&As_l[off]));
            }
            #pragma unroll
            for (int p = 0; p < 2; p++) {
                int off = (wn32 + p * 16 + b_n) * PADK + ko + b_koff;
                uint32_t r0, r1, r2, r3;
                ldsm_x4(r0, r1, r2, r3, smem_u32(&Bs_h[off]));
                bh[2*p][0] = r0; bh[2*p][1] = r1; bh[2*p+1][0] = r2; bh[2*p+1][1] = r3;
                ldsm_x4(r0, r1, r2, r3, smem_u32(&Bs_l[off]));
                bl[2*p][0] = r0; bl[2*p][1] = r1; bl[2*p+1][0] = r2; bl[2*p+1][1] = r3;
            }
            #pragma unroll
            for (int mt = 0; mt < 4; mt++)
                #pragma unroll
                for (int nt = 0; nt < 4; nt++) {
                    float* c = acc[mt][nt];
                    mma_bf16(c[0], c[1], c[2], c[3],
                             ah[mt][0], ah[mt][1], ah[mt][2], ah[mt][3],
                             bh[nt][0], bh[nt][1]);
                    mma_bf16(c[0], c[1], c[2], c[3],
                             ah[mt][0], ah[mt][1], ah[mt][2], ah[mt][3],
                             bl[nt][0], bl[nt][1]);
                    mma_bf16(c[0], c[1], c[2], c[3],
                             al[mt][0], al[mt][1], al[mt][2], al[mt][3],
                             bh[nt][0], bh[nt][1]);
                }
        }
        __syncthreads();
    }

    // epilogue
    #pragma unroll
    for (int mt = 0; mt < 4; mt++) {
        int row = bm + wm64 + mt * 16 + (lane >> 2);
        #pragma unroll
        for (int nt = 0; nt < 4; nt++) {
            int col = bn + wn32 + nt * 8 + (lane & 3) * 2;
            float b0 = 0.f, b1 = 0.f;
            if (BIAS) { b0 = bias[col]; b1 = bias[col + 1]; }
            float* c = acc[mt][nt];
            *(float2*)(C + (size_t)row * N + col)       = make_float2(c[0] + b0, c[1] + b1);
            *(float2*)(C + (size_t)(row + 8) * N + col) = make_float2(c[2] + b0, c[3] + b1);
        }
    }
}

// ---------------------------------------------------------------------------
// Kernel 3: per-head LayerNorm over Dh=64 for q (with *0.125) and k, in place.
// ---------------------------------------------------------------------------
__global__ __launch_bounds__(256) void head_ln(float* __restrict__ q,
                                               float* __restrict__ k)
{
    float* base = blockIdx.y ? k : q;
    float sc    = blockIdx.y ? 1.0f : QSCALE;

    int warp = threadIdx.x >> 5;
    int lane = threadIdx.x & 31;
    int idx  = blockIdx.x * 8 + warp;       // 0 .. TOKENS*HEADS-1
    int token = idx >> 4;
    int h     = idx & 15;

    float2* p = (float2*)(base + (size_t)token * CH + h * DH) + lane;
    float2 v = *p;
    float s  = v.x + v.y;
    float ss = v.x*v.x + v.y*v.y;
    #pragma unroll
    for (int o = 16; o; o >>= 1) {
        s  += __shfl_xor_sync(0xFFFFFFFFu, s,  o);
        ss += __shfl_xor_sync(0xFFFFFFFFu, ss, o);
    }
    float mean = s * (1.0f / DH);
    float var  = ss * (1.0f / DH) - mean * mean;
    float inv  = rsqrtf(var + LN_EPS) * sc;
    v.x = (v.x - mean) * inv;
    v.y = (v.y - mean) * inv;
    *p = v;
}

// ---------------------------------------------------------------------------
// Kernel 4: attention. NO online max needed: after per-head LN, |q|2=1 and
// |k|2=8 so |s|<=8 -> exp(s)<=2981, no overflow. One query row per thread.
// ---------------------------------------------------------------------------
__global__ __launch_bounds__(256, 1) void attn_kernel(const float* __restrict__ q,
                                                      const float* __restrict__ k,
                                                      const float* __restrict__ v,
                                                      float* __restrict__ o)
{
    int bh = blockIdx.x;
    int b  = bh >> 4;
    int h  = bh & 15;
    int t  = threadIdx.x;
    int qi = blockIdx.y * 256 + t;

    const float* qrow = q + ((size_t)(b * SEQ + qi)) * CH + h * DH;
    float qr[DH];
    #pragma unroll
    for (int d4 = 0; d4 < DH/4; d4++) {
        float4 f = ((const float4*)qrow)[d4];
        qr[4*d4+0] = f.x; qr[4*d4+1] = f.y; qr[4*d4+2] = f.z; qr[4*d4+3] = f.w;
    }

    float acc[DH];
    #pragma unroll
    for (int d = 0; d < DH; d++) acc[d] = 0.f;
    float l = 0.f;

    __shared__ float Ks[64][DH];
    __shared__ float Vs[64][DH];

    for (int kt = 0; kt < SEQ; kt += 64) {
        __syncthreads();
        #pragma unroll
        for (int i = 0; i < 4; i++) {
            int f   = t + i * 256;   // float4 index within 64x64 tile
            int row = f >> 4;        // 16 float4 per row
            int col = f & 15;
            size_t gro = ((size_t)(b * SEQ + kt + row)) * CH + h * DH;
            ((float4*)Ks[row])[col] = ((const float4*)(k + gro))[col];
            ((float4*)Vs[row])[col] = ((const float4*)(v + gro))[col];
        }
        __syncthreads();

        #pragma unroll 1
        for (int j = 0; j < 64; j++) {
            float s0 = 0.f, s1 = 0.f, s2 = 0.f, s3 = 0.f;
            #pragma unroll
            for (int d4 = 0; d4 < DH/4; d4++) {
                float4 kk = ((const float4*)Ks[j])[d4];
                s0 += qr[4*d4+0] * kk.x;
                s1 += qr[4*d4+1] * kk.y;
                s2 += qr[4*d4+2] * kk.z;
                s3 += qr[4*d4+3] * kk.w;
            }
            float s = (s0 + s1) + (s2 + s3);
            float p = __expf(s);
            l += p;
            #pragma unroll
            for (int d4 = 0; d4 < DH/4; d4++) {
                float4 vv = ((const float4*)Vs[j])[d4];
                acc[4*d4+0] += p * vv.x;
                acc[4*d4+1] += p * vv.y;
                acc[4*d4+2] += p * vv.z;
                acc[4*d4+3] += p * vv.w;
            }
        }
    }

    float rl = 1.0f / l;
    float* orow = o + ((size_t)(b * SEQ + qi)) * CH + h * DH;
    #pragma unroll
    for (int d4 = 0; d4 < DH/4; d4++) {
        float4 f;
        f.x = acc[4*d4+0] * rl; f.y = acc[4*d4+1] * rl;
        f.z = acc[4*d4+2] * rl; f.w = acc[4*d4+3] * rl;
        ((float4*)orow)[d4] = f;
    }
}

// ---------------------------------------------------------------------------
// Launch
// ---------------------------------------------------------------------------
extern "C" void kernel_launch(void* const* d_in, const int* in_sizes, int n_in,
                              void* d_out, int out_size)
{
    const float* x  = (const float*)d_in[0];
    const float* Wq = (const float*)d_in[1];
    const float* Wk = (const float*)d_in[2];
    const float* Wv = (const float*)d_in[3];
    const float* Wp = (const float*)d_in[4];
    const float* bp = (const float*)d_in[5];
    float* out = (float*)d_out;

    float *p_y, *p_q, *p_k, *p_v, *p_ao;
    cudaGetSymbolAddress((void**)&p_y,  g_y);
    cudaGetSymbolAddress((void**)&p_q,  g_q);
    cudaGetSymbolAddress((void**)&p_k,  g_k);
    cudaGetSymbolAddress((void**)&p_v,  g_v);
    cudaGetSymbolAddress((void**)&p_ao, g_ao);

    // 1. Pre-LN
    ln_rows<<<TOKENS, 256>>>(x, p_y);

    // 2. QKV projections fused into one launch (z selects the weight)
    dim3 gqkv(CH / 128, TOKENS / 128, 3);
    gemm_bf16s<false, true><<<gqkv, 256>>>(p_y, Wq, Wk, Wv, nullptr,
                                           p_q, p_k, p_v, TOKENS, CH, CH);

    // 3. Per-head LN on q (with scale) and k
    head_ln<<<dim3(TOKENS * HEADS / 8, 2), 256>>>(p_q, p_k);

    // 4. Attention
    attn_kernel<<<dim3(BATCH * HEADS, SEQ / 256), 256>>>(p_q, p_k, p_v, p_ao);

    // 5. Output projection + bias
    dim3 gout(CH / 128, TOKENS / 128, 1);
    gemm_bf16s<true, false><<<gout, 256>>>(p_ao, Wp, nullptr, nullptr, bp,
                                           out, nullptr, nullptr, TOKENS, CH, CH);
}

// round 3
// speedup vs baseline: 2.9273x; 1.8551x over previous
#include <cuda_runtime.h>
#include <cuda_bf16.h>
#include <math.h>
#include <stdint.h>

// Problem constants
#define BATCH   16
#define SEQ     1024
#define CH      1024
#define HEADS   16
#define DH      64
#define TOKENS  (BATCH*SEQ)      // 16384
#define LN_EPS  1e-6f
#define QSCALE  0.125f           // Dh^-0.5

// Scratch (device globals: allocation-free per harness rules)
__device__ float    g_y [TOKENS*CH];
__device__ float    g_q [TOKENS*CH];
__device__ float    g_k [TOKENS*CH];
__device__ float    g_v [TOKENS*CH];
__device__ float    g_ao[TOKENS*CH];
// split bf16 planes in [B,H,N,DH] layout
__device__ uint16_t g_qh[TOKENS*CH]; __device__ uint16_t g_ql[TOKENS*CH];
__device__ uint16_t g_kh[TOKENS*CH]; __device__ uint16_t g_kl[TOKENS*CH];
__device__ uint16_t g_vh[TOKENS*CH]; __device__ uint16_t g_vl[TOKENS*CH];

// ---------------------------------------------------------------------------
// helpers
// ---------------------------------------------------------------------------
__device__ __forceinline__ uint32_t smem_u32(const void* p) {
    return (uint32_t)__cvta_generic_to_shared(p);
}
__device__ __forceinline__ void ldsm_x4(uint32_t& r0, uint32_t& r1,
                                        uint32_t& r2, uint32_t& r3, uint32_t addr) {
    asm volatile("ldmatrix.sync.aligned.m8n8.x4.shared.b16 {%0,%1,%2,%3},[%4];"
                 : "=r"(r0), "=r"(r1), "=r"(r2), "=r"(r3) : "r"(addr));
}
__device__ __forceinline__ void ldsm_x4_t(uint32_t& r0, uint32_t& r1,
                                          uint32_t& r2, uint32_t& r3, uint32_t addr) {
    asm volatile("ldmatrix.sync.aligned.m8n8.x4.trans.shared.b16 {%0,%1,%2,%3},[%4];"
                 : "=r"(r0), "=r"(r1), "=r"(r2), "=r"(r3) : "r"(addr));
}
__device__ __forceinline__ void mma_bf16(float* c,
                                         uint32_t a0, uint32_t a1, uint32_t a2, uint32_t a3,
                                         uint32_t b0, uint32_t b1) {
    asm volatile("mma.sync.aligned.m16n8k16.row.col.f32.bf16.bf16.f32 "
                 "{%0,%1,%2,%3},{%4,%5,%6,%7},{%8,%9},{%0,%1,%2,%3};"
                 : "+f"(c[0]), "+f"(c[1]), "+f"(c[2]), "+f"(c[3])
                 : "r"(a0), "r"(a1), "r"(a2), "r"(a3), "r"(b0), "r"(b1));
}
__device__ __forceinline__ uint32_t pack_bf2(float lo, float hi) {
    __nv_bfloat162 t = __floats2bfloat162_rn(lo, hi);
    return *(uint32_t*)&t;
}
__device__ __forceinline__ void split2(float a, float b, uint32_t& hi, uint32_t& lo) {
    __nv_bfloat16 ha = __float2bfloat16(a);
    __nv_bfloat16 hb = __float2bfloat16(b);
    hi = (uint32_t)__bfloat16_as_ushort(ha) | ((uint32_t)__bfloat16_as_ushort(hb) << 16);
    lo = pack_bf2(a - __bfloat162float(ha), b - __bfloat162float(hb));
}
__device__ __forceinline__ void split_pack(float4 f, uint32_t& h01, uint32_t& h23,
                                           uint32_t& l01, uint32_t& l23) {
    split2(f.x, f.y, h01, l01);
    split2(f.z, f.w, h23, l23);
}

// ---------------------------------------------------------------------------
// Kernel 1: LayerNorm over last dim (C=1024), no affine. One block per row.
// ---------------------------------------------------------------------------
__global__ __launch_bounds__(256) void ln_rows(const float* __restrict__ x,
                                               float* __restrict__ y)
{
    int row = blockIdx.x;
    int t = threadIdx.x;
    const float4* xr = (const float4*)(x + (size_t)row * CH);
    float4* yr = (float4*)(y + (size_t)row * CH);

    float4 v = xr[t];
    float s  = v.x + v.y + v.z + v.w;
    float ss = v.x*v.x + v.y*v.y + v.z*v.z + v.w*v.w;

    #pragma unroll
    for (int o = 16; o; o >>= 1) {
        s  += __shfl_xor_sync(0xFFFFFFFFu, s,  o);
        ss += __shfl_xor_sync(0xFFFFFFFFu, ss, o);
    }
    __shared__ float sh[16];
    int w = t >> 5, l = t & 31;
    if (l == 0) { sh[w] = s; sh[8 + w] = ss; }
    __syncthreads();
    float S = 0.f, SS = 0.f;
    #pragma unroll
    for (int i = 0; i < 8; i++) { S += sh[i]; SS += sh[8 + i]; }

    float mean = S * (1.0f / CH);
    float var  = SS * (1.0f / CH) - mean * mean;
    float inv  = rsqrtf(var + LN_EPS);

    v.x = (v.x - mean) * inv;
    v.y = (v.y - mean) * inv;
    v.z = (v.z - mean) * inv;
    v.w = (v.w - mean) * inv;
    yr[t] = v;
}

// ---------------------------------------------------------------------------
// Kernel 2: split-bf16 tensor-core GEMM (NT). 128x128x32 tile, 256 threads.
// ---------------------------------------------------------------------------
#define BK   32
#define PADK 40

template<bool BIAS, bool QKV3>
__global__ __launch_bounds__(256) void gemm_bf16s(const float* __restrict__ A,
                                                  const float* __restrict__ B0,
                                                  const float* __restrict__ B1,
                                                  const float* __restrict__ B2,
                                                  const float* __restrict__ bias,
                                                  float* __restrict__ C0,
                                                  float* __restrict__ C1,
                                                  float* __restrict__ C2,
                                                  int M, int N, int K)
{
    __shared__ __align__(16) uint16_t As_h[128 * PADK];
    __shared__ __align__(16) uint16_t As_l[128 * PADK];
    __shared__ __align__(16) uint16_t Bs_h[128 * PADK];
    __shared__ __align__(16) uint16_t Bs_l[128 * PADK];

    const float* B = B0;
    float* C = C0;
    if (QKV3) {
        if (blockIdx.z == 1) { B = B1; C = C1; }
        else if (blockIdx.z == 2) { B = B2; C = C2; }
    }

    int t    = threadIdx.x;
    int lane = t & 31;
    int warp = t >> 5;
    int wm64 = (warp >> 2) * 64;
    int wn32 = (warp & 3) * 32;
    int bm = blockIdx.y * 128;
    int bn = blockIdx.x * 128;

    const float* Ag = A + (size_t)bm * K;
    const float* Bg = B + (size_t)bn * K;

    float acc[4][4][4];
    #pragma unroll
    for (int i = 0; i < 4; i++)
        #pragma unroll
        for (int j = 0; j < 4; j++)
            #pragma unroll
            for (int c = 0; c < 4; c++) acc[i][j][c] = 0.f;

    float4 ra[4], rb[4];
    int ldrow[4], ldc4[4];
    #pragma unroll
    for (int i = 0; i < 4; i++) {
        int f = t + i * 256;
        ldrow[i] = f >> 3;
        ldc4[i]  = f & 7;
    }

    #pragma unroll
    for (int i = 0; i < 4; i++) {
        ra[i] = *(const float4*)(Ag + (size_t)ldrow[i] * K + ldc4[i] * 4);
        rb[i] = *(const float4*)(Bg + (size_t)ldrow[i] * K + ldc4[i] * 4);
    }

    int a_r    = lane & 15;
    int a_koff = (lane >> 4) << 3;
    int b_n    = (lane & 7) + ((lane >> 4) << 3);
    int b_koff = ((lane >> 3) & 1) << 3;

    for (int k0 = 0; k0 < K; k0 += BK) {
        #pragma unroll
        for (int i = 0; i < 4; i++) {
            uint32_t h01, h23, l01, l23;
            int off = ldrow[i] * PADK + ldc4[i] * 4;
            split_pack(ra[i], h01, h23, l01, l23);
            *(uint2*)&As_h[off] = make_uint2(h01, h23);
            *(uint2*)&As_l[off] = make_uint2(l01, l23);
            split_pack(rb[i], h01, h23, l01, l23);
            *(uint2*)&Bs_h[off] = make_uint2(h01, h23);
            *(uint2*)&Bs_l[off] = make_uint2(l01, l23);
        }
        __syncthreads();

        if (k0 + BK < K) {
            #pragma unroll
            for (int i = 0; i < 4; i++) {
                ra[i] = *(const float4*)(Ag + (size_t)ldrow[i] * K + k0 + BK + ldc4[i] * 4);
                rb[i] = *(const float4*)(Bg + (size_t)ldrow[i] * K + k0 + BK + ldc4[i] * 4);
            }
        }

        #pragma unroll
        for (int kc = 0; kc < 2; kc++) {
            int ko = kc * 16;
            uint32_t ah[4][4], al[4][4], bh[4][2], bl[4][2];
            #pragma unroll
            for (int mt = 0; mt < 4; mt++) {
                int off = (wm64 + mt * 16 + a_r) * PADK + ko + a_koff;
                ldsm_x4(ah[mt][0], ah[mt][1], ah[mt][2], ah[mt][3], smem_u32(&As_h[off]));
                ldsm_x4(al[mt][0], al[mt][1], al[mt][2], al[mt][3], smem_u32(&As_l[off]));
            }
            #pragma unroll
            for (int p = 0; p < 2; p++) {
                int off = (wn32 + p * 16 + b_n) * PADK + ko + b_koff;
                uint32_t r0, r1, r2, r3;
                ldsm_x4(r0, r1, r2, r3, smem_u32(&Bs_h[off]));
                bh[2*p][0] = r0; bh[2*p][1] = r1; bh[2*p+1][0] = r2; bh[2*p+1][1] = r3;
                ldsm_x4(r0, r1, r2, r3, smem_u32(&Bs_l[off]));
                bl[2*p][0] = r0; bl[2*p][1] = r1; bl[2*p+1][0] = r2; bl[2*p+1][1] = r3;
            }
            #pragma unroll
            for (int mt = 0; mt < 4; mt++)
                #pragma unroll
                for (int nt = 0; nt < 4; nt++) {
                    float* c = acc[mt][nt];
                    mma_bf16(c, ah[mt][0], ah[mt][1], ah[mt][2], ah[mt][3],
                             bh[nt][0], bh[nt][1]);
                    mma_bf16(c, ah[mt][0], ah[mt][1], ah[mt][2], ah[mt][3],
                             bl[nt][0], bl[nt][1]);
                    mma_bf16(c, al[mt][0], al[mt][1], al[mt][2], al[mt][3],
                             bh[nt][0], bh[nt][1]);
                }
        }
        __syncthreads();
    }

    #pragma unroll
    for (int mt = 0; mt < 4; mt++) {
        int row = bm + wm64 + mt * 16 + (lane >> 2);
        #pragma unroll
        for (int nt = 0; nt < 4; nt++) {
            int col = bn + wn32 + nt * 8 + (lane & 3) * 2;
            float b0 = 0.f, b1 = 0.f;
            if (BIAS) { b0 = bias[col]; b1 = bias[col + 1]; }
            float* c = acc[mt][nt];
            *(float2*)(C + (size_t)row * N + col)       = make_float2(c[0] + b0, c[1] + b1);
            *(float2*)(C + (size_t)(row + 8) * N + col) = make_float2(c[2] + b0, c[3] + b1);
        }
    }
}

// ---------------------------------------------------------------------------
// Kernel 3: per-head LN (q: with *0.125, k) or passthrough (v), then split
// to bf16 hi/lo planes in [B,H,N,DH] layout. One warp per (token, head).
// blockIdx.y: 0=q, 1=k, 2=v.
// ---------------------------------------------------------------------------
__global__ __launch_bounds__(256) void split_ln(const float* __restrict__ qs,
                                                const float* __restrict__ ks,
                                                const float* __restrict__ vs,
                                                uint16_t* __restrict__ qh,
                                                uint16_t* __restrict__ ql,
                                                uint16_t* __restrict__ kh,
                                                uint16_t* __restrict__ kl,
                                                uint16_t* __restrict__ vh,
                                                uint16_t* __restrict__ vl)
{
    int z = blockIdx.y;
    const float* src = (z == 0) ? qs : (z == 1) ? ks : vs;
    uint16_t* dh = (z == 0) ? qh : (z == 1) ? kh : vh;
    uint16_t* dl = (z == 0) ? ql : (z == 1) ? kl : vl;

    int warp = threadIdx.x >> 5;
    int lane = threadIdx.x & 31;
    int idx  = blockIdx.x * 8 + warp;       // (token, head) id
    int token = idx >> 4;
    int h     = idx & 15;

    float2 val = *((const float2*)(src + (size_t)token * CH + h * DH) + lane);

    if (z < 2) {
        float s  = val.x + val.y;
        float ss = val.x*val.x + val.y*val.y;
        #pragma unroll
        for (int o = 16; o; o >>= 1) {
            s  += __shfl_xor_sync(0xFFFFFFFFu, s,  o);
            ss += __shfl_xor_sync(0xFFFFFFFFu, ss, o);
        }
        float mean = s * (1.0f / DH);
        float var  = ss * (1.0f / DH) - mean * mean;
        float inv  = rsqrtf(var + LN_EPS) * (z == 0 ? QSCALE : 1.0f);
        val.x = (val.x - mean) * inv;
        val.y = (val.y - mean) * inv;
    }

    size_t plane = ((((size_t)(token >> 10)) * HEADS + h) * SEQ + (token & 1023)) * DH
                 + lane * 2;
    uint32_t hi, lo;
    split2(val.x, val.y, hi, lo);
    *(uint32_t*)(dh + plane) = hi;
    *(uint32_t*)(dl + plane) = lo;
}

// ---------------------------------------------------------------------------
// Kernel 4: tensor-core flash attention (no max tracking: |s|<=8).
// Block: 256 threads (8 warps), Q tile 128 rows (16/warp), KV tile 64 keys.
// 3-pass split-bf16 for both QK^T and P*V. Output fp32 [token][CH].
// ---------------------------------------------------------------------------
#define SSTR 72   // padded bf16 row stride (144B = 9*16B, conflict-free ldmatrix)

__global__ __launch_bounds__(256, 1) void attn_tc(const uint16_t* __restrict__ qh,
                                                  const uint16_t* __restrict__ ql,
                                                  const uint16_t* __restrict__ kh,
                                                  const uint16_t* __restrict__ kl,
                                                  const uint16_t* __restrict__ vh,
                                                  const uint16_t* __restrict__ vl,
                                                  float* __restrict__ o)
{
    extern __shared__ __align__(16) uint16_t sm[];
    uint16_t* Qh = sm;                    // 128*SSTR
    uint16_t* Ql = Qh + 128 * SSTR;
    uint16_t* Kh = Ql + 128 * SSTR;       // 64*SSTR each below
    uint16_t* Kl = Kh + 64 * SSTR;
    uint16_t* Vh = Kl + 64 * SSTR;
    uint16_t* Vl = Vh + 64 * SSTR;

    int bh = blockIdx.x;                  // b*16+h
    int qb = blockIdx.y * 128;
    int t = threadIdx.x, lane = t & 31, warp = t >> 5;
    size_t plane = (size_t)bh * SEQ * DH;

    // Load Q tile (128x64 hi+lo)
    #pragma unroll
    for (int i = 0; i < 4; i++) {
        int f = t + i * 256;
        int row = f >> 3, c = (f & 7) * 8;
        size_t src = plane + (size_t)(qb + row) * DH + c;
        *(uint4*)&Qh[row * SSTR + c] = *(const uint4*)(qh + src);
        *(uint4*)&Ql[row * SSTR + c] = *(const uint4*)(ql + src);
    }
    __syncthreads();

    // Q fragments (persist)
    uint32_t qfh[4][4], qfl[4][4];
    int a_r = lane & 15, a_ko = (lane >> 4) << 3;
    #pragma unroll
    for (int ch = 0; ch < 4; ch++) {
        int off = (warp * 16 + a_r) * SSTR + ch * 16 + a_ko;
        ldsm_x4(qfh[ch][0], qfh[ch][1], qfh[ch][2], qfh[ch][3], smem_u32(&Qh[off]));
        ldsm_x4(qfl[ch][0], qfl[ch][1], qfl[ch][2], qfl[ch][3], smem_u32(&Ql[off]));
    }

    float oacc[8][4];
    #pragma unroll
    for (int i = 0; i < 8; i++)
        #pragma unroll
        for (int j = 0; j < 4; j++) oacc[i][j] = 0.f;
    float l0 = 0.f, l1 = 0.f;

    int b_n  = (lane & 7) + ((lane >> 4) << 3);
    int b_ko = ((lane >> 3) & 1) << 3;
    int v_r  = lane & 15;
    int v_co = (lane >> 4) * 8;

    for (int kt = 0; kt < SEQ; kt += 64) {
        __syncthreads();
        #pragma unroll
        for (int i = 0; i < 2; i++) {
            int f = t + i * 256;
            int row = f >> 3, c = (f & 7) * 8;
            size_t src = plane + (size_t)(kt + row) * DH + c;
            *(uint4*)&Kh[row * SSTR + c] = *(const uint4*)(kh + src);
            *(uint4*)&Kl[row * SSTR + c] = *(const uint4*)(kl + src);
            *(uint4*)&Vh[row * SSTR + c] = *(const uint4*)(vh + src);
            *(uint4*)&Vl[row * SSTR + c] = *(const uint4*)(vl + src);
        }
        __syncthreads();

        // ----- S = Q K^T (fp32 via 3-pass split) -----
        float sacc[8][4];
        #pragma unroll
        for (int i = 0; i < 8; i++)
            #pragma unroll
            for (int j = 0; j < 4; j++) sacc[i][j] = 0.f;

        #pragma unroll
        for (int kp = 0; kp < 4; kp++) {
            #pragma unroll
            for (int ch = 0; ch < 4; ch++) {
                int off = (kp * 16 + b_n) * SSTR + ch * 16 + b_ko;
                uint32_t h0,h1,h2,h3, e0,e1,e2,e3;
                ldsm_x4(h0,h1,h2,h3, smem_u32(&Kh[off]));
                ldsm_x4(e0,e1,e2,e3, smem_u32(&Kl[off]));
                float* c0 = sacc[2*kp];
                float* c1 = sacc[2*kp+1];
                mma_bf16(c0, qfh[ch][0],qfh[ch][1],qfh[ch][2],qfh[ch][3], h0,h1);
                mma_bf16(c0, qfh[ch][0],qfh[ch][1],qfh[ch][2],qfh[ch][3], e0,e1);
                mma_bf16(c0, qfl[ch][0],qfl[ch][1],qfl[ch][2],qfl[ch][3], h0,h1);
                mma_bf16(c1, qfh[ch][0],qfh[ch][1],qfh[ch][2],qfh[ch][3], h2,h3);
                mma_bf16(c1, qfh[ch][0],qfh[ch][1],qfh[ch][2],qfh[ch][3], e2,e3);
                mma_bf16(c1, qfl[ch][0],qfl[ch][1],qfl[ch][2],qfl[ch][3], h2,h3);
            }
        }

        // ----- softmax numerators (no max needed) + l accumulation -----
        #pragma unroll
        for (int nt = 0; nt < 8; nt++) {
            float p0 = __expf(sacc[nt][0]);
            float p1 = __expf(sacc[nt][1]);
            float p2 = __expf(sacc[nt][2]);
            float p3 = __expf(sacc[nt][3]);
            sacc[nt][0] = p0; sacc[nt][1] = p1;
            sacc[nt][2] = p2; sacc[nt][3] = p3;
            l0 += p0 + p1;
            l1 += p2 + p3;
        }

        // ----- O += P V (3-pass split; C-frag -> A-frag reuse) -----
        #pragma unroll
        for (int j = 0; j < 4; j++) {
            uint32_t ph[4], pl[4];
            float* ca = sacc[2*j];
            float* cb = sacc[2*j+1];
            split2(ca[0], ca[1], ph[0], pl[0]);
            split2(ca[2], ca[3], ph[1], pl[1]);
            split2(cb[0], cb[1], ph[2], pl[2]);
            split2(cb[2], cb[3], ph[3], pl[3]);
            #pragma unroll
            for (int dp = 0; dp < 4; dp++) {
                int off = (j * 16 + v_r) * SSTR + dp * 16 + v_co;
                uint32_t b0,b1,b2,b3, f0,f1,f2,f3;
                ldsm_x4_t(b0,b1,b2,b3, smem_u32(&Vh[off]));
                ldsm_x4_t(f0,f1,f2,f3, smem_u32(&Vl[off]));
                float* o0 = oacc[2*dp];
                float* o1 = oacc[2*dp+1];
                mma_bf16(o0, ph[0],ph[1],ph[2],ph[3], b0,b1);
                mma_bf16(o0, ph[0],ph[1],ph[2],ph[3], f0,f1);
                mma_bf16(o0, pl[0],pl[1],pl[2],pl[3], b0,b1);
                mma_bf16(o1, ph[0],ph[1],ph[2],ph[3], b2,b3);
                mma_bf16(o1, ph[0],ph[1],ph[2],ph[3], f2,f3);
                mma_bf16(o1, pl[0],pl[1],pl[2],pl[3], b2,b3);
            }
        }
    }

    // reduce l across the 4 lanes sharing a row
    l0 += __shfl_xor_sync(0xFFFFFFFFu, l0, 1);
    l0 += __shfl_xor_sync(0xFFFFFFFFu, l0, 2);
    l1 += __shfl_xor_sync(0xFFFFFFFFu, l1, 1);
    l1 += __shfl_xor_sync(0xFFFFFFFFu, l1, 2);
    float rl0 = 1.0f / l0, rl1 = 1.0f / l1;

    // write O to [token][CH] fp32
    int b = bh >> 4, h = bh & 15;
    int r0 = qb + warp * 16 + (lane >> 2);
    size_t base0 = ((size_t)(b * SEQ + r0)) * CH + h * DH + (lane & 3) * 2;
    size_t base1 = base0 + 8 * CH;
    #pragma unroll
    for (int nt = 0; nt < 8; nt++) {
        *(float2*)(o + base0 + nt * 8) = make_float2(oacc[nt][0] * rl0, oacc[nt][1] * rl0);
        *(float2*)(o + base1 + nt * 8) = make_float2(oacc[nt][2] * rl1, oacc[nt][3] * rl1);
    }
}

// ---------------------------------------------------------------------------
// Launch
// ---------------------------------------------------------------------------
extern "C" void kernel_launch(void* const* d_in, const int* in_sizes, int n_in,
                              void* d_out, int out_size)
{
    const float* x  = (const float*)d_in[0];
    const float* Wq = (const float*)d_in[1];
    const float* Wk = (const float*)d_in[2];
    const float* Wv = (const float*)d_in[3];
    const float* Wp = (const float*)d_in[4];
    const float* bp = (const float*)d_in[5];
    float* out = (float*)d_out;

    float *p_y, *p_q, *p_k, *p_v, *p_ao;
    uint16_t *p_qh, *p_ql, *p_kh, *p_kl, *p_vh, *p_vl;
    cudaGetSymbolAddress((void**)&p_y,  g_y);
    cudaGetSymbolAddress((void**)&p_q,  g_q);
    cudaGetSymbolAddress((void**)&p_k,  g_k);
    cudaGetSymbolAddress((void**)&p_v,  g_v);
    cudaGetSymbolAddress((void**)&p_ao, g_ao);
    cudaGetSymbolAddress((void**)&p_qh, g_qh);
    cudaGetSymbolAddress((void**)&p_ql, g_ql);
    cudaGetSymbolAddress((void**)&p_kh, g_kh);
    cudaGetSymbolAddress((void**)&p_kl, g_kl);
    cudaGetSymbolAddress((void**)&p_vh, g_vh);
    cudaGetSymbolAddress((void**)&p_vl, g_vl);

    // 1. Pre-LN
    ln_rows<<<TOKENS, 256>>>(x, p_y);

    // 2. QKV projections fused into one launch (z selects the weight)
    dim3 gqkv(CH / 128, TOKENS / 128, 3);
    gemm_bf16s<false, true><<<gqkv, 256>>>(p_y, Wq, Wk, Wv, nullptr,
                                           p_q, p_k, p_v, TOKENS, CH, CH);

    // 3. Per-head LN + split to bf16 planes (q,k LN'd, v passthrough)
    split_ln<<<dim3(TOKENS * HEADS / 8, 3), 256>>>(p_q, p_k, p_v,
                                                   p_qh, p_ql, p_kh, p_kl, p_vh, p_vl);

    // 4. Tensor-core flash attention
    const int ATT_SMEM = (128 * SSTR * 2 + 64 * SSTR * 4) * 2;   // bytes
    cudaFuncSetAttribute(attn_tc, cudaFuncAttributeMaxDynamicSharedMemorySize, ATT_SMEM);
    attn_tc<<<dim3(BATCH * HEADS, SEQ / 128), 256, ATT_SMEM>>>(p_qh, p_ql, p_kh, p_kl,
                                                               p_vh, p_vl, p_ao);

    // 5. Output projection + bias
    dim3 gout(CH / 128, TOKENS / 128, 1);
    gemm_bf16s<true, false><<<gout, 256>>>(p_ao, Wp, nullptr, nullptr, bp,
                                           out, nullptr, nullptr, TOKENS, CH, CH);
}

// round 4
// speedup vs baseline: 3.3443x; 1.1425x over previous
#include <cuda_runtime.h>
#include <cuda_bf16.h>
#include <math.h>
#include <stdint.h>

// Problem constants
#define BATCH   16
#define SEQ     1024
#define CH      1024
#define HEADS   16
#define DH      64
#define TOKENS  (BATCH*SEQ)      // 16384
#define LN_EPS  1e-6f
#define QSCALE  0.125f           // Dh^-0.5

// Scratch (device globals: allocation-free per harness rules)
__device__ uint16_t g_yh[TOKENS*CH]; __device__ uint16_t g_yl[TOKENS*CH];
__device__ uint16_t g_wh[4*CH*CH];   __device__ uint16_t g_wl[4*CH*CH];
__device__ float    g_q [TOKENS*CH];
__device__ float    g_k [TOKENS*CH];
__device__ float    g_v [TOKENS*CH];
// split bf16 planes in [B,H,N,DH] layout
__device__ uint16_t g_qh[TOKENS*CH]; __device__ uint16_t g_ql[TOKENS*CH];
__device__ uint16_t g_kh[TOKENS*CH]; __device__ uint16_t g_kl[TOKENS*CH];
__device__ uint16_t g_vh[TOKENS*CH]; __device__ uint16_t g_vl[TOKENS*CH];
// attention output planes in [token][CH] layout
__device__ uint16_t g_aoh[TOKENS*CH]; __device__ uint16_t g_aol[TOKENS*CH];

// ---------------------------------------------------------------------------
// helpers
// ---------------------------------------------------------------------------
__device__ __forceinline__ uint32_t smem_u32(const void* p) {
    return (uint32_t)__cvta_generic_to_shared(p);
}
__device__ __forceinline__ void ldsm_x4(uint32_t& r0, uint32_t& r1,
                                        uint32_t& r2, uint32_t& r3, uint32_t addr) {
    asm volatile("ldmatrix.sync.aligned.m8n8.x4.shared.b16 {%0,%1,%2,%3},[%4];"
                 : "=r"(r0), "=r"(r1), "=r"(r2), "=r"(r3) : "r"(addr));
}
__device__ __forceinline__ void ldsm_x4_t(uint32_t& r0, uint32_t& r1,
                                          uint32_t& r2, uint32_t& r3, uint32_t addr) {
    asm volatile("ldmatrix.sync.aligned.m8n8.x4.trans.shared.b16 {%0,%1,%2,%3},[%4];"
                 : "=r"(r0), "=r"(r1), "=r"(r2), "=r"(r3) : "r"(addr));
}
__device__ __forceinline__ void mma_bf16(float* c,
                                         uint32_t a0, uint32_t a1, uint32_t a2, uint32_t a3,
                                         uint32_t b0, uint32_t b1) {
    asm volatile("mma.sync.aligned.m16n8k16.row.col.f32.bf16.bf16.f32 "
                 "{%0,%1,%2,%3},{%4,%5,%6,%7},{%8,%9},{%0,%1,%2,%3};"
                 : "+f"(c[0]), "+f"(c[1]), "+f"(c[2]), "+f"(c[3])
                 : "r"(a0), "r"(a1), "r"(a2), "r"(a3), "r"(b0), "r"(b1));
}
__device__ __forceinline__ uint32_t pack_bf2(float lo, float hi) {
    __nv_bfloat162 t = __floats2bfloat162_rn(lo, hi);
    return *(uint32_t*)&t;
}
__device__ __forceinline__ void split2(float a, float b, uint32_t& hi, uint32_t& lo) {
    __nv_bfloat16 ha = __float2bfloat16(a);
    __nv_bfloat16 hb = __float2bfloat16(b);
    hi = (uint32_t)__bfloat16_as_ushort(ha) | ((uint32_t)__bfloat16_as_ushort(hb) << 16);
    lo = pack_bf2(a - __bfloat162float(ha), b - __bfloat162float(hb));
}
__device__ __forceinline__ void split_pack(float4 f, uint32_t& h01, uint32_t& h23,
                                           uint32_t& l01, uint32_t& l23) {
    split2(f.x, f.y, h01, l01);
    split2(f.z, f.w, h23, l23);
}

#define CP16(dst, src) asm volatile("cp.async.cg.shared.global [%0],[%1],16;" :: "r"(dst), "l"(src))
#define CPCOMMIT()     asm volatile("cp.async.commit_group;")
#define CPWAIT1()      asm volatile("cp.async.wait_group 1;")
#define CPWAIT0()      asm volatile("cp.async.wait_group 0;")

// ---------------------------------------------------------------------------
// Kernel 1: LayerNorm over C=1024 + direct split to bf16 hi/lo planes.
// ---------------------------------------------------------------------------
__global__ __launch_bounds__(256) void ln_split_rows(const float* __restrict__ x,
                                                     uint16_t* __restrict__ yh,
                                                     uint16_t* __restrict__ yl)
{
    int row = blockIdx.x;
    int t = threadIdx.x;
    const float4* xr = (const float4*)(x + (size_t)row * CH);

    float4 v = xr[t];
    float s  = v.x + v.y + v.z + v.w;
    float ss = v.x*v.x + v.y*v.y + v.z*v.z + v.w*v.w;

    #pragma unroll
    for (int o = 16; o; o >>= 1) {
        s  += __shfl_xor_sync(0xFFFFFFFFu, s,  o);
        ss += __shfl_xor_sync(0xFFFFFFFFu, ss, o);
    }
    __shared__ float sh[16];
    int w = t >> 5, l = t & 31;
    if (l == 0) { sh[w] = s; sh[8 + w] = ss; }
    __syncthreads();
    float S = 0.f, SS = 0.f;
    #pragma unroll
    for (int i = 0; i < 8; i++) { S += sh[i]; SS += sh[8 + i]; }

    float mean = S * (1.0f / CH);
    float var  = SS * (1.0f / CH) - mean * mean;
    float inv  = rsqrtf(var + LN_EPS);

    v.x = (v.x - mean) * inv;
    v.y = (v.y - mean) * inv;
    v.z = (v.z - mean) * inv;
    v.w = (v.w - mean) * inv;

    uint32_t h01, h23, l01, l23;
    split_pack(v, h01, h23, l01, l23);
    size_t off = (size_t)row * CH + t * 4;
    *(uint2*)(yh + off) = make_uint2(h01, h23);
    *(uint2*)(yl + off) = make_uint2(l01, l23);
}

// ---------------------------------------------------------------------------
// Kernel 1b: split weights (4 matrices) to bf16 hi/lo planes.
// ---------------------------------------------------------------------------
__global__ __launch_bounds__(256) void w_split(const float* __restrict__ W0,
                                               const float* __restrict__ W1,
                                               const float* __restrict__ W2,
                                               const float* __restrict__ W3,
                                               uint16_t* __restrict__ wh,
                                               uint16_t* __restrict__ wl)
{
    int z = blockIdx.y;
    const float* W = (z == 0) ? W0 : (z == 1) ? W1 : (z == 2) ? W2 : W3;
    size_t base = (size_t)z * CH * CH;
    size_t off  = ((size_t)blockIdx.x * 256 + threadIdx.x) * 4;

    float4 f = *(const float4*)(W + off);
    uint32_t h01, h23, l01, l23;
    split_pack(f, h01, h23, l01, l23);
    *(uint2*)(wh + base + off) = make_uint2(h01, h23);
    *(uint2*)(wl + base + off) = make_uint2(l01, l23);
}

// ---------------------------------------------------------------------------
// Kernel 2: pure-bf16 tensor-core GEMM (NT), cp.async double-buffered.
// C[m,n] = sum_k A[m,k]*B[n,k] (3-pass split sum) (+bias).
// 128x128x32 tile, 256 threads, 2-stage pipeline.
// ---------------------------------------------------------------------------
#define BK    32
#define PADK  40
#define PLANE (128*PADK)   // bf16 elements per smem plane

template<bool BIAS, bool QKV3>
__global__ __launch_bounds__(256) void gemm_async(const uint16_t* __restrict__ Ah,
                                                  const uint16_t* __restrict__ Al,
                                                  const uint16_t* __restrict__ Bh_,
                                                  const uint16_t* __restrict__ Bl_,
                                                  const float* __restrict__ bias,
                                                  float* __restrict__ C0,
                                                  float* __restrict__ C1,
                                                  float* __restrict__ C2,
                                                  int M, int N, int K)
{
    extern __shared__ __align__(16) uint16_t smg[];

    const uint16_t* Bh = Bh_;
    const uint16_t* Bl = Bl_;
    float* C = C0;
    if (QKV3) {
        size_t zo = (size_t)blockIdx.z * N * K;
        Bh += zo; Bl += zo;
        if (blockIdx.z == 1) C = C1;
        else if (blockIdx.z == 2) C = C2;
    }

    int t    = threadIdx.x;
    int lane = t & 31;
    int warp = t >> 5;
    int wm64 = (warp >> 2) * 64;
    int wn32 = (warp & 3) * 32;
    int bm = blockIdx.y * 128;
    int bn = blockIdx.x * 128;

    const uint16_t* Agh = Ah + (size_t)bm * K;
    const uint16_t* Agl = Al + (size_t)bm * K;
    const uint16_t* Bgh = Bh + (size_t)bn * K;
    const uint16_t* Bgl = Bl + (size_t)bn * K;

    uint32_t smem_base = smem_u32(smg);

    float acc[4][4][4];
    #pragma unroll
    for (int i = 0; i < 4; i++)
        #pragma unroll
        for (int j = 0; j < 4; j++)
            #pragma unroll
            for (int c = 0; c < 4; c++) acc[i][j][c] = 0.f;

    // per-thread cp.async chunks: 2 per plane (512 chunks of 16B per plane)
    int c0r = t >> 2,          c0c = (t & 3) * 8;
    int c1r = (t + 256) >> 2,  c1c = ((t + 256) & 3) * 8;

    auto issue = [&](int stage, int k0) {
        uint32_t sb = smem_base + stage * (4 * PLANE * 2);
        uint32_t s0 = sb + (c0r * PADK + c0c) * 2;
        uint32_t s1 = sb + (c1r * PADK + c1c) * 2;
        CP16(s0 + 0*PLANE*2, Agh + (size_t)c0r * K + k0 + c0c);
        CP16(s1 + 0*PLANE*2, Agh + (size_t)c1r * K + k0 + c1c);
        CP16(s0 + 1*PLANE*2, Agl + (size_t)c0r * K + k0 + c0c);
        CP16(s1 + 1*PLANE*2, Agl + (size_t)c1r * K + k0 + c1c);
        CP16(s0 + 2*PLANE*2, Bgh + (size_t)c0r * K + k0 + c0c);
        CP16(s1 + 2*PLANE*2, Bgh + (size_t)c1r * K + k0 + c1c);
        CP16(s0 + 3*PLANE*2, Bgl + (size_t)c0r * K + k0 + c0c);
        CP16(s1 + 3*PLANE*2, Bgl + (size_t)c1r * K + k0 + c1c);
        CPCOMMIT();
    };

    int a_r    = lane & 15;
    int a_koff = (lane >> 4) << 3;
    int b_n    = (lane & 7) + ((lane >> 4) << 3);
    int b_koff = ((lane >> 3) & 1) << 3;

    const int T = 1024 / BK;   // K == 1024 (compile-time here)
    issue(0, 0);
    issue(1, BK);

    for (int i = 0; i < T; i++) {
        if (i + 1 < T) { CPWAIT1(); } else { CPWAIT0(); }
        __syncthreads();

        uint16_t* sAh = smg + (i & 1) * 4 * PLANE;
        uint16_t* sAl = sAh + PLANE;
        uint16_t* sBh = sAl + PLANE;
        uint16_t* sBl = sBh + PLANE;

        #pragma unroll
        for (int kc = 0; kc < 2; kc++) {
            int ko = kc * 16;
            uint32_t ah[4][4], al[4][4], bh[4][2], bl[4][2];
            #pragma unroll
            for (int mt = 0; mt < 4; mt++) {
                int off = (wm64 + mt * 16 + a_r) * PADK + ko + a_koff;
                ldsm_x4(ah[mt][0], ah[mt][1], ah[mt][2], ah[mt][3], smem_u32(&sAh[off]));
                ldsm_x4(al[mt][0], al[mt][1], al[mt][2], al[mt][3], smem_u32(&sAl[off]));
            }
            #pragma unroll
            for (int p = 0; p < 2; p++) {
                int off = (wn32 + p * 16 + b_n) * PADK + ko + b_koff;
                uint32_t r0, r1, r2, r3;
                ldsm_x4(r0, r1, r2, r3, smem_u32(&sBh[off]));
                bh[2*p][0] = r0; bh[2*p][1] = r1; bh[2*p+1][0] = r2; bh[2*p+1][1] = r3;
                ldsm_x4(r0, r1, r2, r3, smem_u32(&sBl[off]));
                bl[2*p][0] = r0; bl[2*p][1] = r1; bl[2*p+1][0] = r2; bl[2*p+1][1] = r3;
            }
            #pragma unroll
            for (int mt = 0; mt < 4; mt++)
                #pragma unroll
                for (int nt = 0; nt < 4; nt++) {
                    float* c = acc[mt][nt];
                    mma_bf16(c, ah[mt][0], ah[mt][1], ah[mt][2], ah[mt][3],
                             bh[nt][0], bh[nt][1]);
                    mma_bf16(c, ah[mt][0], ah[mt][1], ah[mt][2], ah[mt][3],
                             bl[nt][0], bl[nt][1]);
                    mma_bf16(c, al[mt][0], al[mt][1], al[mt][2], al[mt][3],
                             bh[nt][0], bh[nt][1]);
                }
        }
        __syncthreads();
        if (i + 2 < T) issue(i & 1, (i + 2) * BK);
    }

    #pragma unroll
    for (int mt = 0; mt < 4; mt++) {
        int row = bm + wm64 + mt * 16 + (lane >> 2);
        #pragma unroll
        for (int nt = 0; nt < 4; nt++) {
            int col = bn + wn32 + nt * 8 + (lane & 3) * 2;
            float b0 = 0.f, b1 = 0.f;
            if (BIAS) { b0 = bias[col]; b1 = bias[col + 1]; }
            float* c = acc[mt][nt];
            *(float2*)(C + (size_t)row * N + col)       = make_float2(c[0] + b0, c[1] + b1);
            *(float2*)(C + (size_t)(row + 8) * N + col) = make_float2(c[2] + b0, c[3] + b1);
        }
    }
}

// ---------------------------------------------------------------------------
// Kernel 3: per-head LN (q *0.125, k) or passthrough (v); split to bf16 planes
// in [B,H,N,DH] layout. One warp per (token, head). blockIdx.y: 0=q,1=k,2=v.
// ---------------------------------------------------------------------------
__global__ __launch_bounds__(256) void split_ln(const float* __restrict__ qs,
                                                const float* __restrict__ ks,
                                                const float* __restrict__ vs,
                                                uint16_t* __restrict__ qh,
                                                uint16_t* __restrict__ ql,
                                                uint16_t* __restrict__ kh,
                                                uint16_t* __restrict__ kl,
                                                uint16_t* __restrict__ vh,
                                                uint16_t* __restrict__ vl)
{
    int z = blockIdx.y;
    const float* src = (z == 0) ? qs : (z == 1) ? ks : vs;
    uint16_t* dh = (z == 0) ? qh : (z == 1) ? kh : vh;
    uint16_t* dl = (z == 0) ? ql : (z == 1) ? kl : vl;

    int warp = threadIdx.x >> 5;
    int lane = threadIdx.x & 31;
    int idx  = blockIdx.x * 8 + warp;
    int token = idx >> 4;
    int h     = idx & 15;

    float2 val = *((const float2*)(src + (size_t)token * CH + h * DH) + lane);

    if (z < 2) {
        float s  = val.x + val.y;
        float ss = val.x*val.x + val.y*val.y;
        #pragma unroll
        for (int o = 16; o; o >>= 1) {
            s  += __shfl_xor_sync(0xFFFFFFFFu, s,  o);
            ss += __shfl_xor_sync(0xFFFFFFFFu, ss, o);
        }
        float mean = s * (1.0f / DH);
        float var  = ss * (1.0f / DH) - mean * mean;
        float inv  = rsqrtf(var + LN_EPS) * (z == 0 ? QSCALE : 1.0f);
        val.x = (val.x - mean) * inv;
        val.y = (val.y - mean) * inv;
    }

    size_t plane = ((((size_t)(token >> 10)) * HEADS + h) * SEQ + (token & 1023)) * DH
                 + lane * 2;
    uint32_t hi, lo;
    split2(val.x, val.y, hi, lo);
    *(uint32_t*)(dh + plane) = hi;
    *(uint32_t*)(dl + plane) = lo;
}

// ---------------------------------------------------------------------------
// Kernel 4: tensor-core flash attention (no max tracking: |s|<=8).
// Q tile 128 rows resident; KV tiles 64 keys, cp.async double-buffered.
// Output written as split bf16 planes in [token][CH] layout.
// ---------------------------------------------------------------------------
#define SSTR    72
#define KV_B    (4*64*SSTR)        // bf16 elements per KV stage (4 planes)

__global__ __launch_bounds__(256, 1) void attn_tc(const uint16_t* __restrict__ qh,
                                                  const uint16_t* __restrict__ ql,
                                                  const uint16_t* __restrict__ kh,
                                                  const uint16_t* __restrict__ kl,
                                                  const uint16_t* __restrict__ vh,
                                                  const uint16_t* __restrict__ vl,
                                                  uint16_t* __restrict__ aoh,
                                                  uint16_t* __restrict__ aol)
{
    extern __shared__ __align__(16) uint16_t sm[];
    uint16_t* Qh = sm;                       // 128*SSTR
    uint16_t* Ql = Qh + 128 * SSTR;
    uint16_t* KV = Ql + 128 * SSTR;          // 2 stages of KV_B

    int bh = blockIdx.x;
    int qb = blockIdx.y * 128;
    int t = threadIdx.x, lane = t & 31, warp = t >> 5;
    size_t plane = (size_t)bh * SEQ * DH;

    // Load Q tile (sync, once)
    #pragma unroll
    for (int i = 0; i < 4; i++) {
        int f = t + i * 256;
        int row = f >> 3, c = (f & 7) * 8;
        size_t src = plane + (size_t)(qb + row) * DH + c;
        *(uint4*)&Qh[row * SSTR + c] = *(const uint4*)(qh + src);
        *(uint4*)&Ql[row * SSTR + c] = *(const uint4*)(ql + src);
    }

    // cp.async KV chunk geometry: 512 chunks/plane, 2 per thread
    int k0r = t >> 3,         k0c = (t & 7) * 8;
    int k1r = (t + 256) >> 3, k1c = ((t + 256) & 7) * 8;
    uint32_t kv_base = smem_u32(KV);

    auto issue_kv = [&](int stage, int kt) {
        uint32_t sb = kv_base + stage * (KV_B * 2);
        uint32_t s0 = sb + (k0r * SSTR + k0c) * 2;
        uint32_t s1 = sb + (k1r * SSTR + k1c) * 2;
        size_t g0 = plane + (size_t)(kt + k0r) * DH + k0c;
        size_t g1 = plane + (size_t)(kt + k1r) * DH + k1c;
        const int PL = 64 * SSTR * 2;   // bytes per plane
        CP16(s0 + 0*PL, kh + g0);  CP16(s1 + 0*PL, kh + g1);
        CP16(s0 + 1*PL, kl + g0);  CP16(s1 + 1*PL, kl + g1);
        CP16(s0 + 2*PL, vh + g0);  CP16(s1 + 2*PL, vh + g1);
        CP16(s0 + 3*PL, vl + g0);  CP16(s1 + 3*PL, vl + g1);
        CPCOMMIT();
    };

    issue_kv(0, 0);
    issue_kv(1, 64);
    __syncthreads();   // Q tile visible

    // Q fragments (persist)
    uint32_t qfh[4][4], qfl[4][4];
    int a_r = lane & 15, a_ko = (lane >> 4) << 3;
    #pragma unroll
    for (int ch = 0; ch < 4; ch++) {
        int off = (warp * 16 + a_r) * SSTR + ch * 16 + a_ko;
        ldsm_x4(qfh[ch][0], qfh[ch][1], qfh[ch][2], qfh[ch][3], smem_u32(&Qh[off]));
        ldsm_x4(qfl[ch][0], qfl[ch][1], qfl[ch][2], qfl[ch][3], smem_u32(&Ql[off]));
    }

    float oacc[8][4];
    #pragma unroll
    for (int i = 0; i < 8; i++)
        #pragma unroll
        for (int j = 0; j < 4; j++) oacc[i][j] = 0.f;
    float l0 = 0.f, l1 = 0.f;

    int b_n  = (lane & 7) + ((lane >> 4) << 3);
    int b_ko = ((lane >> 3) & 1) << 3;
    int v_r  = lane & 15;
    int v_co = (lane >> 4) * 8;

    const int T = SEQ / 64;   // 16 tiles
    for (int i = 0; i < T; i++) {
        if (i + 1 < T) { CPWAIT1(); } else { CPWAIT0(); }
        __syncthreads();

        uint16_t* Kh = KV + (i & 1) * KV_B;
        uint16_t* Kl = Kh + 64 * SSTR;
        uint16_t* Vh = Kl + 64 * SSTR;
        uint16_t* Vl = Vh + 64 * SSTR;

        // ----- S = Q K^T -----
        float sacc[8][4];
        #pragma unroll
        for (int a = 0; a < 8; a++)
            #pragma unroll
            for (int c = 0; c < 4; c++) sacc[a][c] = 0.f;

        #pragma unroll
        for (int kp = 0; kp < 4; kp++) {
            #pragma unroll
            for (int ch = 0; ch < 4; ch++) {
                int off = (kp * 16 + b_n) * SSTR + ch * 16 + b_ko;
                uint32_t h0,h1,h2,h3, e0,e1,e2,e3;
                ldsm_x4(h0,h1,h2,h3, smem_u32(&Kh[off]));
                ldsm_x4(e0,e1,e2,e3, smem_u32(&Kl[off]));
                float* c0 = sacc[2*kp];
                float* c1 = sacc[2*kp+1];
                mma_bf16(c0, qfh[ch][0],qfh[ch][1],qfh[ch][2],qfh[ch][3], h0,h1);
                mma_bf16(c0, qfh[ch][0],qfh[ch][1],qfh[ch][2],qfh[ch][3], e0,e1);
                mma_bf16(c0, qfl[ch][0],qfl[ch][1],qfl[ch][2],qfl[ch][3], h0,h1);
                mma_bf16(c1, qfh[ch][0],qfh[ch][1],qfh[ch][2],qfh[ch][3], h2,h3);
                mma_bf16(c1, qfh[ch][0],qfh[ch][1],qfh[ch][2],qfh[ch][3], e2,e3);
                mma_bf16(c1, qfl[ch][0],qfl[ch][1],qfl[ch][2],qfl[ch][3], h2,h3);
            }
        }

        // ----- exp + l accumulation -----
        #pragma unroll
        for (int nt = 0; nt < 8; nt++) {
            float p0 = __expf(sacc[nt][0]);
            float p1 = __expf(sacc[nt][1]);
            float p2 = __expf(sacc[nt][2]);
            float p3 = __expf(sacc[nt][3]);
            sacc[nt][0] = p0; sacc[nt][1] = p1;
            sacc[nt][2] = p2; sacc[nt][3] = p3;
            l0 += p0 + p1;
            l1 += p2 + p3;
        }

        // ----- O += P V -----
        #pragma unroll
        for (int j = 0; j < 4; j++) {
            uint32_t ph[4], pl[4];
            float* ca = sacc[2*j];
            float* cb = sacc[2*j+1];
            split2(ca[0], ca[1], ph[0], pl[0]);
            split2(ca[2], ca[3], ph[1], pl[1]);
            split2(cb[0], cb[1], ph[2], pl[2]);
            split2(cb[2], cb[3], ph[3], pl[3]);
            #pragma unroll
            for (int dp = 0; dp < 4; dp++) {
                int off = (j * 16 + v_r) * SSTR + dp * 16 + v_co;
                uint32_t b0,b1,b2,b3, f0,f1,f2,f3;
                ldsm_x4_t(b0,b1,b2,b3, smem_u32(&Vh[off]));
                ldsm_x4_t(f0,f1,f2,f3, smem_u32(&Vl[off]));
                float* o0 = oacc[2*dp];
                float* o1 = oacc[2*dp+1];
                mma_bf16(o0, ph[0],ph[1],ph[2],ph[3], b0,b1);
                mma_bf16(o0, ph[0],ph[1],ph[2],ph[3], f0,f1);
                mma_bf16(o0, pl[0],pl[1],pl[2],pl[3], b0,b1);
                mma_bf16(o1, ph[0],ph[1],ph[2],ph[3], b2,b3);
                mma_bf16(o1, ph[0],ph[1],ph[2],ph[3], f2,f3);
                mma_bf16(o1, pl[0],pl[1],pl[2],pl[3], b2,b3);
            }
        }

        __syncthreads();
        if (i + 2 < T) issue_kv(i & 1, (i + 2) * 64);
    }

    // reduce l across the 4 lanes sharing a row
    l0 += __shfl_xor_sync(0xFFFFFFFFu, l0, 1);
    l0 += __shfl_xor_sync(0xFFFFFFFFu, l0, 2);
    l1 += __shfl_xor_sync(0xFFFFFFFFu, l1, 1);
    l1 += __shfl_xor_sync(0xFFFFFFFFu, l1, 2);
    float rl0 = 1.0f / l0, rl1 = 1.0f / l1;

    // write O as split bf16 planes in [token][CH]
    int b = bh >> 4, h = bh & 15;
    int r0 = qb + warp * 16 + (lane >> 2);
    size_t base0 = ((size_t)(b * SEQ + r0)) * CH + h * DH + (lane & 3) * 2;
    size_t base1 = base0 + 8 * CH;
    #pragma unroll
    for (int nt = 0; nt < 8; nt++) {
        uint32_t hi, lo;
        split2(oacc[nt][0] * rl0, oacc[nt][1] * rl0, hi, lo);
        *(uint32_t*)(aoh + base0 + nt * 8) = hi;
        *(uint32_t*)(aol + base0 + nt * 8) = lo;
        split2(oacc[nt][2] * rl1, oacc[nt][3] * rl1, hi, lo);
        *(uint32_t*)(aoh + base1 + nt * 8) = hi;
        *(uint32_t*)(aol + base1 + nt * 8) = lo;
    }
}

// ---------------------------------------------------------------------------
// Launch
// ---------------------------------------------------------------------------
extern "C" void kernel_launch(void* const* d_in, const int* in_sizes, int n_in,
                              void* d_out, int out_size)
{
    const float* x  = (const float*)d_in[0];
    const float* Wq = (const float*)d_in[1];
    const float* Wk = (const float*)d_in[2];
    const float* Wv = (const float*)d_in[3];
    const float* Wp = (const float*)d_in[4];
    const float* bp = (const float*)d_in[5];
    float* out = (float*)d_out;

    uint16_t *p_yh, *p_yl, *p_wh, *p_wl;
    float *p_q, *p_k, *p_v;
    uint16_t *p_qh, *p_ql, *p_kh, *p_kl, *p_vh, *p_vl, *p_aoh, *p_aol;
    cudaGetSymbolAddress((void**)&p_yh, g_yh);
    cudaGetSymbolAddress((void**)&p_yl, g_yl);
    cudaGetSymbolAddress((void**)&p_wh, g_wh);
    cudaGetSymbolAddress((void**)&p_wl, g_wl);
    cudaGetSymbolAddress((void**)&p_q,  g_q);
    cudaGetSymbolAddress((void**)&p_k,  g_k);
    cudaGetSymbolAddress((void**)&p_v,  g_v);
    cudaGetSymbolAddress((void**)&p_qh, g_qh);
    cudaGetSymbolAddress((void**)&p_ql, g_ql);
    cudaGetSymbolAddress((void**)&p_kh, g_kh);
    cudaGetSymbolAddress((void**)&p_kl, g_kl);
    cudaGetSymbolAddress((void**)&p_vh, g_vh);
    cudaGetSymbolAddress((void**)&p_vl, g_vl);
    cudaGetSymbolAddress((void**)&p_aoh, g_aoh);
    cudaGetSymbolAddress((void**)&p_aol, g_aol);

    const int GEMM_SMEM = 2 * 4 * PLANE * 2;                     // 81920 B
    const int ATT_SMEM  = (2 * 128 * SSTR + 2 * KV_B) * 2;       // 110592 B
    static int configured = 0;
    if (!configured) {
        cudaFuncSetAttribute(gemm_async<false, true>,
                             cudaFuncAttributeMaxDynamicSharedMemorySize, GEMM_SMEM);
        cudaFuncSetAttribute(gemm_async<true, false>,
                             cudaFuncAttributeMaxDynamicSharedMemorySize, GEMM_SMEM);
        cudaFuncSetAttribute(attn_tc,
                             cudaFuncAttributeMaxDynamicSharedMemorySize, ATT_SMEM);
        configured = 1;
    }

    // 1. Pre-LN fused with bf16 split
    ln_split_rows<<<TOKENS, 256>>>(x, p_yh, p_yl);

    // 1b. Split weights (cheap, memory-bound)
    w_split<<<dim3(CH * CH / 1024, 4), 256>>>(Wq, Wk, Wv, Wp, p_wh, p_wl);

    // 2. QKV projections (z selects weight plane)
    dim3 gqkv(CH / 128, TOKENS / 128, 3);
    gemm_async<false, true><<<gqkv, 256, GEMM_SMEM>>>(p_yh, p_yl, p_wh, p_wl, nullptr,
                                                      p_q, p_k, p_v, TOKENS, CH, CH);

    // 3. Per-head LN + split to planes
    split_ln<<<dim3(TOKENS * HEADS / 8, 3), 256>>>(p_q, p_k, p_v,
                                                   p_qh, p_ql, p_kh, p_kl, p_vh, p_vl);

    // 4. Tensor-core flash attention (writes split planes)
    attn_tc<<<dim3(BATCH * HEADS, SEQ / 128), 256, ATT_SMEM>>>(p_qh, p_ql, p_kh, p_kl,
                                                               p_vh, p_vl, p_aoh, p_aol);

    // 5. Output projection + bias
    dim3 gout(CH / 128, TOKENS / 128, 1);
    gemm_async<true, false><<<gout, 256, GEMM_SMEM>>>(p_aoh, p_aol,
                                                      p_wh + (size_t)3 * CH * CH,
                                                      p_wl + (size_t)3 * CH * CH,
                                                      bp, out, nullptr, nullptr,
                                                      TOKENS, CH, CH);
}